// round 17
// baseline (speedup 1.0000x reference)
#include <cuda_runtime.h>
#include <math_constants.h>

// PhiCell hysteresis scan: out_i = clamp(out_{i-1}, x_i, x_i + 1), x_i = in_i*k.
// Clamp maps compose associatively -> 3-pass scan (measured-best structure).
// R17: ITEMS 16->32 in phase1/phase3 (8 front-batched LDG.128 per thread) to
// double memory-level parallelism; 4-way split composite + 4 concurrent
// output recurrence chains via quarter-point restart maps.

#define BLOCK 256
#define ITEMS 32
#define CHUNK (BLOCK * ITEMS)   // 8192 elements per block
#define MAXB  1024

struct CH { float L, H; };

__device__ __forceinline__ CH ch_id() {
    CH r; r.L = -CUDART_INF_F; r.H = CUDART_INF_F; return r;
}
// compose: apply a FIRST, then b
__device__ __forceinline__ CH ch_comp(CH a, CH b) {
    CH r;
    r.L = fminf(fmaxf(a.L, b.L), b.H);
    r.H = fminf(fmaxf(a.H, b.L), b.H);
    return r;
}

__device__ float2 g_part[MAXB];
__device__ float2 g_excl[MAXB];

__device__ __forceinline__ CH warp_incl_scan(CH v, int lane) {
#pragma unroll
    for (int off = 1; off < 32; off <<= 1) {
        float pl = __shfl_up_sync(0xffffffffu, v.L, off);
        float ph = __shfl_up_sync(0xffffffffu, v.H, off);
        if (lane >= off) { CH p; p.L = pl; p.H = ph; v = ch_comp(p, v); }
    }
    return v;
}

// exclusive composite of all lower-threadIdx threads (identity for t==0)
__device__ CH block_excl_scan(CH v) {
    __shared__ CH ws[BLOCK / 32];
    int lane = threadIdx.x & 31;
    int wid  = threadIdx.x >> 5;

    CH vi = warp_incl_scan(v, lane);
    if (lane == 31) ws[wid] = vi;
    __syncthreads();
    if (wid == 0) {
        CH w = (lane < BLOCK / 32) ? ws[lane] : ch_id();
        w = warp_incl_scan(w, lane);
        if (lane < BLOCK / 32) ws[lane] = w;
    }
    __syncthreads();
    CH wp = (wid > 0) ? ws[wid - 1] : ch_id();

    float pl = __shfl_up_sync(0xffffffffu, vi.L, 1);
    float ph = __shfl_up_sync(0xffffffffu, vi.H, 1);
    CH ve = ch_id();
    if (lane > 0) { ve.L = pl; ve.H = ph; }
    return ch_comp(wp, ve);
}

__device__ __forceinline__ void absorb(CH& c, float a) {
    float ap = a + 1.0f;
    c.L = fminf(fmaxf(c.L, a), ap);
    c.H = fminf(fmaxf(c.H, a), ap);
}

__device__ __forceinline__ void absorb4(CH& c, float4 v, float k) {
    absorb(c, v.x * k); absorb(c, v.y * k);
    absorb(c, v.z * k); absorb(c, v.w * k);
}

// Phase 1: per-block composite; 8 loads in flight, 4 independent chains
__global__ void __launch_bounds__(BLOCK)
k_phase1(const float* __restrict__ in, const float* __restrict__ kw) {
    float k = __ldg(kw);
    int base = blockIdx.x * CHUNK + threadIdx.x * ITEMS;
    const float4* p = reinterpret_cast<const float4*>(in + base);

    float4 v0 = __ldg(&p[0]);
    float4 v1 = __ldg(&p[1]);
    float4 v2 = __ldg(&p[2]);
    float4 v3 = __ldg(&p[3]);
    float4 v4 = __ldg(&p[4]);
    float4 v5 = __ldg(&p[5]);
    float4 v6 = __ldg(&p[6]);
    float4 v7 = __ldg(&p[7]);

    CH c0 = ch_id(), c1 = ch_id(), c2 = ch_id(), c3 = ch_id();
    absorb4(c0, v0, k); absorb4(c1, v2, k);
    absorb4(c2, v4, k); absorb4(c3, v6, k);
    absorb4(c0, v1, k); absorb4(c1, v3, k);
    absorb4(c2, v5, k); absorb4(c3, v7, k);
    CH c = ch_comp(ch_comp(c0, c1), ch_comp(c2, c3));

    CH e = block_excl_scan(c);
    if (threadIdx.x == BLOCK - 1) {
        CH t = ch_comp(e, c);
        g_part[blockIdx.x] = make_float2(t.L, t.H);
    }
}

// Phase 2: exclusive scan of block composites (single block)
__global__ void __launch_bounds__(BLOCK)
k_phase2(int nb) {
    int t = threadIdx.x;
    const int P = MAXB / BLOCK;               // 4
    CH loc[P];
    CH c = ch_id();
#pragma unroll
    for (int j = 0; j < P; j++) {
        int i = t * P + j;
        CH x = ch_id();
        if (i < nb) { float2 f = g_part[i]; x.L = f.x; x.H = f.y; }
        c = ch_comp(c, x);
        loc[j] = c;                           // local inclusive
    }
    CH te = block_excl_scan(c);
#pragma unroll
    for (int j = 0; j < P; j++) {
        int i = t * P + j;
        if (i < nb) {
            CH e = (j == 0) ? te : ch_comp(te, loc[j - 1]);
            g_excl[i] = make_float2(e.L, e.H);
        }
    }
}

// Phase 3: apply prefixes, 4 concurrent output recurrence chains
__global__ void __launch_bounds__(BLOCK)
k_phase3(const float* __restrict__ in, const float* __restrict__ kw,
         const float* __restrict__ stt, float* __restrict__ out,
         int n, int out_size) {
    float k  = __ldg(kw);
    int base = blockIdx.x * CHUNK + threadIdx.x * ITEMS;
    const float4* p = reinterpret_cast<const float4*>(in + base);

    float4 v0 = __ldg(&p[0]);
    float4 v1 = __ldg(&p[1]);
    float4 v2 = __ldg(&p[2]);
    float4 v3 = __ldg(&p[3]);
    float4 v4 = __ldg(&p[4]);
    float4 v5 = __ldg(&p[5]);
    float4 v6 = __ldg(&p[6]);
    float4 v7 = __ldg(&p[7]);

    // scale in place
    v0.x *= k; v0.y *= k; v0.z *= k; v0.w *= k;
    v1.x *= k; v1.y *= k; v1.z *= k; v1.w *= k;
    v2.x *= k; v2.y *= k; v2.z *= k; v2.w *= k;
    v3.x *= k; v3.y *= k; v3.z *= k; v3.w *= k;
    v4.x *= k; v4.y *= k; v4.z *= k; v4.w *= k;
    v5.x *= k; v5.y *= k; v5.z *= k; v5.w *= k;
    v6.x *= k; v6.y *= k; v6.z *= k; v6.w *= k;
    v7.x *= k; v7.y *= k; v7.z *= k; v7.w *= k;

    // 4 independent quarter composites (each covers 8 consecutive elements)
    CH c0 = ch_id(), c1 = ch_id(), c2 = ch_id(), c3 = ch_id();
    absorb4(c0, v0, 1.0f); absorb4(c1, v2, 1.0f);
    absorb4(c2, v4, 1.0f); absorb4(c3, v6, 1.0f);
    absorb4(c0, v1, 1.0f); absorb4(c1, v3, 1.0f);
    absorb4(c2, v5, 1.0f); absorb4(c3, v7, 1.0f);
    CH c = ch_comp(ch_comp(c0, c1), ch_comp(c2, c3));

    CH e = block_excl_scan(c);

    float2 be2 = g_excl[blockIdx.x];
    CH be; be.L = be2.x; be.H = be2.y;
    CH m0 = ch_comp(be, e);                   // map before elem 0
    CH m1 = ch_comp(m0, c0);                  // before elem 8
    CH m2 = ch_comp(m1, c1);                  // before elem 16
    CH m3 = ch_comp(m2, c2);                  // before elem 24

    float s0 = __ldg(stt);
    float p0r = fminf(fmaxf(s0, m0.L), m0.H);
    float p1r = fminf(fmaxf(s0, m1.L), m1.H);
    float p2r = fminf(fmaxf(s0, m2.L), m2.H);
    float p3r = fminf(fmaxf(s0, m3.L), m3.H);

    // 4 concurrent recurrence chains, interleaved
    float4 r0, r1, r2, r3, r4, r5, r6, r7;
#define STEP(pv, a, dst) pv = fminf(fmaxf(pv, (a)), (a) + 1.0f); dst = pv
    STEP(p0r, v0.x, r0.x); STEP(p1r, v2.x, r2.x); STEP(p2r, v4.x, r4.x); STEP(p3r, v6.x, r6.x);
    STEP(p0r, v0.y, r0.y); STEP(p1r, v2.y, r2.y); STEP(p2r, v4.y, r4.y); STEP(p3r, v6.y, r6.y);
    STEP(p0r, v0.z, r0.z); STEP(p1r, v2.z, r2.z); STEP(p2r, v4.z, r4.z); STEP(p3r, v6.z, r6.z);
    STEP(p0r, v0.w, r0.w); STEP(p1r, v2.w, r2.w); STEP(p2r, v4.w, r4.w); STEP(p3r, v6.w, r6.w);
    STEP(p0r, v1.x, r1.x); STEP(p1r, v3.x, r3.x); STEP(p2r, v5.x, r5.x); STEP(p3r, v7.x, r7.x);
    STEP(p0r, v1.y, r1.y); STEP(p1r, v3.y, r3.y); STEP(p2r, v5.y, r5.y); STEP(p3r, v7.y, r7.y);
    STEP(p0r, v1.z, r1.z); STEP(p1r, v3.z, r3.z); STEP(p2r, v5.z, r5.z); STEP(p3r, v7.z, r7.z);
    STEP(p0r, v1.w, r1.w); STEP(p1r, v3.w, r3.w); STEP(p2r, v5.w, r5.w); STEP(p3r, v7.w, r7.w);
#undef STEP

    float4* o = reinterpret_cast<float4*>(out + base);
    __stcs(&o[0], r0);
    __stcs(&o[1], r1);
    __stcs(&o[2], r2);
    __stcs(&o[3], r3);
    __stcs(&o[4], r4);
    __stcs(&o[5], r5);
    __stcs(&o[6], r6);
    __stcs(&o[7], r7);

    // new_state appended after T outputs, if present
    if (base + ITEMS == n && out_size > n) out[n] = p3r;
}

extern "C" void kernel_launch(void* const* d_in, const int* in_sizes, int n_in,
                              void* d_out, int out_size) {
    const float* in  = (const float*)d_in[0];   // inputs [1, T]
    const float* stt = (const float*)d_in[1];   // state  [1, 1]
    const float* kw  = (const float*)d_in[2];   // kernel [1, 1]
    float* out = (float*)d_out;

    int n  = in_sizes[0];
    int nb = n / CHUNK;                         // 2^23 / 8192 = 1024 blocks

    k_phase1<<<nb, BLOCK>>>(in, kw);
    k_phase2<<<1, BLOCK>>>(nb);
    k_phase3<<<nb, BLOCK>>>(in, kw, stt, out, n, out_size);
}